// round 2
// baseline (speedup 1.0000x reference)
#include <cuda_runtime.h>

// Shapes: pred/target (2,2,128,128,128) fp32, contiguous.
// N = 8,388,608 elements. Lines per axis pass: 65,536 per tensor.
#define NTOT 8388608
#define BC_STRIDE 2097152   // 128*128*128
#define D_STRIDE  16384     // 128*128
#define H_STRIDE  128
#define NLINES    65536

__device__ float g_pred[NTOT];
__device__ float g_target[NTOT];
__device__ double g_acc;

__global__ void k_zero() { g_acc = 0.0; }

// ---------------------------------------------------------------------------
// Pass 1: squared EDT along W (contiguous axis), binary input.
// out[x] = min_y (g0[y] + (x-y)^2), g0 in {0, 1e12}  ==  d(x)^2 where d is
// the distance to the nearest background voxel (or 1e12 if none in line).
// Block = 128 threads, handles 128 lines via a shared tile (conflict-free pad).
// ---------------------------------------------------------------------------
__global__ void k_pass1(const float* __restrict__ pred,
                        const float* __restrict__ target) {
    __shared__ unsigned short tile[128][130];
    const float* src = (blockIdx.y == 0) ? pred : target;
    float* dst = (blockIdx.y == 0) ? g_pred : g_target;
    const int tid = threadIdx.x;
    const long base = (long)blockIdx.x * 16384;  // 128 lines * 128 elems

    // Coalesced load: mask (1 = foreground/BIG, 0 = background/zero)
    #pragma unroll 8
    for (int r = 0; r < 128; r++)
        tile[r][tid] = (src[base + r * 128 + tid] >= 0.5f) ? 1 : 0;
    __syncthreads();

    // Each thread sweeps one line (row tid). Forward then backward.
    {
        int d = 999;
        #pragma unroll 4
        for (int w = 0; w < 128; w++) {
            if (tile[tid][w] == 0) d = 0;
            else d = (d < 999) ? d + 1 : 999;
            tile[tid][w] = (unsigned short)d;
        }
        int db = 999;
        #pragma unroll 4
        for (int w = 127; w >= 0; w--) {
            int df = tile[tid][w];              // 0 iff background site
            if (df == 0) db = 0;
            else db = (db < 999) ? db + 1 : 999;
            tile[tid][w] = (unsigned short)(df < db ? df : db);
        }
    }
    __syncthreads();

    // Coalesced store of squared distances
    #pragma unroll 8
    for (int r = 0; r < 128; r++) {
        int dv = tile[r][tid];
        dst[base + r * 128 + tid] = (dv <= 127) ? (float)(dv * dv) : 1e12f;
    }
}

// ---------------------------------------------------------------------------
// Exact Felzenszwalb 1-D squared-EDT (min-plus with parabolas), n = 128.
// In-place on a strided line. One thread per line; lines arranged so that
// consecutive threads touch consecutive addresses (coalesced).
// ---------------------------------------------------------------------------
template <int STRIDE>
__device__ __forceinline__ void edt_line_inplace(float* __restrict__ g) {
    float fq[128];          // f[i] + i*i
    unsigned char v[128];
    float z[129];

    #pragma unroll 4
    for (int i = 0; i < 128; i++)
        fq[i] = g[(long)i * STRIDE] + (float)(i * i);

    int k = 0;
    v[0] = 0; z[0] = -1e30f; z[1] = 1e30f;
    for (int q = 1; q < 128; q++) {
        float s;
        while (true) {
            int vk = v[k];
            s = __fdividef(fq[q] - fq[vk], (float)(2 * (q - vk)));
            if (s <= z[k]) k--;
            else break;
        }
        k++;
        v[k] = (unsigned char)q;
        z[k] = s;
        z[k + 1] = 1e30f;
    }
    k = 0;
    for (int x = 0; x < 128; x++) {
        while (z[k + 1] < (float)x) k++;
        int vk = v[k];
        g[(long)x * STRIDE] = fq[vk] + (float)(x * (x - 2 * vk));
    }
}

// Same, but writes results to a register/local output array (no global store).
template <int STRIDE>
__device__ __forceinline__ void edt_line_eval(const float* __restrict__ g,
                                              float* __restrict__ out) {
    float fq[128];
    unsigned char v[128];
    float z[129];

    #pragma unroll 4
    for (int i = 0; i < 128; i++)
        fq[i] = g[(long)i * STRIDE] + (float)(i * i);

    int k = 0;
    v[0] = 0; z[0] = -1e30f; z[1] = 1e30f;
    for (int q = 1; q < 128; q++) {
        float s;
        while (true) {
            int vk = v[k];
            s = __fdividef(fq[q] - fq[vk], (float)(2 * (q - vk)));
            if (s <= z[k]) k--;
            else break;
        }
        k++;
        v[k] = (unsigned char)q;
        z[k] = s;
        z[k + 1] = 1e30f;
    }
    k = 0;
    for (int x = 0; x < 128; x++) {
        while (z[k + 1] < (float)x) k++;
        int vk = v[k];
        out[x] = fq[vk] + (float)(x * (x - 2 * vk));
    }
}

// ---------------------------------------------------------------------------
// Pass 2: EDT along H, in place. Thread t -> line (bc, d, w); consecutive w
// per consecutive threads -> coalesced strided access.
// ---------------------------------------------------------------------------
__global__ void k_pass2() {
    float* gbuf = (blockIdx.y == 0) ? g_pred : g_target;
    int t = blockIdx.x * 128 + threadIdx.x;          // 0..65535
    int w  = t & 127;
    int d  = (t >> 7) & 127;
    int bc = t >> 14;
    float* base = gbuf + (long)bc * BC_STRIDE + (long)d * D_STRIDE + w;
    edt_line_inplace<H_STRIDE>(base);
}

// ---------------------------------------------------------------------------
// Pass 3 (along D) fused with the loss reduction:
//   acc += (pred - target)^2 * (edtD(g_pred) + edtD(g_target))
// No global writes of g needed. Block-reduce doubles, one atomicAdd per block.
// ---------------------------------------------------------------------------
__global__ void k_pass3_reduce(const float* __restrict__ pred,
                               const float* __restrict__ target) {
    int t = blockIdx.x * 128 + threadIdx.x;          // 0..65535
    int w  = t & 127;
    int h  = (t >> 7) & 127;
    int bc = t >> 14;
    const long base = (long)bc * BC_STRIDE + (long)h * H_STRIDE + w;

    float op[128];
    edt_line_eval<D_STRIDE>(g_pred + base, op);

    double acc = 0.0;
    {
        const float* gt = g_target + base;
        float fq[128];
        unsigned char v[128];
        float z[129];
        #pragma unroll 4
        for (int i = 0; i < 128; i++)
            fq[i] = gt[(long)i * D_STRIDE] + (float)(i * i);

        int k = 0;
        v[0] = 0; z[0] = -1e30f; z[1] = 1e30f;
        for (int q = 1; q < 128; q++) {
            float s;
            while (true) {
                int vk = v[k];
                s = __fdividef(fq[q] - fq[vk], (float)(2 * (q - vk)));
                if (s <= z[k]) k--;
                else break;
            }
            k++;
            v[k] = (unsigned char)q;
            z[k] = s;
            z[k + 1] = 1e30f;
        }
        k = 0;
        for (int x = 0; x < 128; x++) {
            while (z[k + 1] < (float)x) k++;
            int vk = v[k];
            float dt_val = fq[vk] + (float)(x * (x - 2 * vk));
            long idx = base + (long)x * D_STRIDE;
            float e = pred[idx] - target[idx];
            acc += (double)(e * e * (op[x] + dt_val));
        }
    }

    __shared__ double sd[128];
    sd[threadIdx.x] = acc;
    __syncthreads();
    #pragma unroll
    for (int s = 64; s > 0; s >>= 1) {
        if (threadIdx.x < s) sd[threadIdx.x] += sd[threadIdx.x + s];
        __syncthreads();
    }
    if (threadIdx.x == 0) atomicAdd(&g_acc, sd[0]);
}

__global__ void k_final(float* __restrict__ out, const int* __restrict__ is_avg) {
    double m = g_acc / (double)NTOT;   // mean over all elements
    if (*is_avg == 0) m *= 2.0;        // * pred.shape[0]
    out[0] = (float)m;
}

extern "C" void kernel_launch(void* const* d_in, const int* in_sizes, int n_in,
                              void* d_out, int out_size) {
    const float* pred   = (const float*)d_in[0];
    const float* target = (const float*)d_in[1];
    const int*   is_avg = (const int*)d_in[2];
    float* out = (float*)d_out;

    k_zero<<<1, 1>>>();
    dim3 g12(NLINES / 128, 2);
    k_pass1<<<g12, 128>>>(pred, target);
    k_pass2<<<g12, 128>>>();
    k_pass3_reduce<<<NLINES / 128, 128>>>(pred, target);
    k_final<<<1, 1>>>(out, is_avg);
}

// round 5
// speedup vs baseline: 1.2887x; 1.2887x over previous
#include <cuda_runtime.h>

// pred/target: (2,2,128,128,128) fp32 contiguous.
#define NTOT 8388608
#define BC_STRIDE 2097152   // 128^3
#define D_STRIDE  16384     // 128^2
#define H_STRIDE  128

__device__ float g_pred[NTOT];
__device__ float g_target[NTOT];
__device__ double g_acc;

__global__ void k_zero() { g_acc = 0.0; }

// ---------------------------------------------------------------------------
// Fused pass1 (W axis, binary two-sweep) + pass2 (H axis, exact Felzenszwalb)
// on one contiguous (bc,d) slab of 128x128 held in a u8 shared tile.
// grid = (512, 2 tensors), block = 128 threads.
//   pass1: thread = row h, sweep w forward/backward, store dist (<=127, 255=inf)
//   pass2: thread = column w, lower-envelope over h, write g to global (coalesced)
// ---------------------------------------------------------------------------
__global__ void __launch_bounds__(128) k_pass12(const float* __restrict__ pred,
                                                const float* __restrict__ target) {
    __shared__ unsigned char dist[128][132];   // pad 132: conflict-free both ways
    const float* src = (blockIdx.y == 0) ? pred : target;
    float* dst = (blockIdx.y == 0) ? g_pred : g_target;
    const int tid = threadIdx.x;
    const long base = (long)blockIdx.x * 16384;   // slab is contiguous

    // mask load (coalesced): 255 = foreground (BIG), 0 = background
    #pragma unroll 8
    for (int r = 0; r < 128; r++)
        dist[r][tid] = (src[base + r * 128 + tid] >= 0.5f) ? 255 : 0;
    __syncthreads();

    // pass1: two integer sweeps along w (thread = row tid)
    {
        unsigned char* row = dist[tid];
        int d = 255;
        #pragma unroll 4
        for (int w = 0; w < 128; w++) {
            d = (row[w] == 0) ? 0 : min(d + 1, 255);
            row[w] = (unsigned char)d;
        }
        int db = 255;
        #pragma unroll 4
        for (int w = 127; w >= 0; w--) {
            int df = row[w];
            db = (df == 0) ? 0 : min(db + 1, 255);
            row[w] = (unsigned char)min(df, db);
        }
    }
    __syncthreads();

    // pass2: Felzenszwalb along h (thread = column tid), fq read from shared.
    // fq(i) = g(i) + i^2 ; g = d^2 (exact small int) or 1e12 (i^2 absorbed by rounding)
    unsigned char v[128];
    float z[129];
    #define FQ(i) ({ int _dv = dist[(i)][tid]; \
                     (_dv == 255) ? 1e12f : (float)(_dv * _dv + (i) * (i)); })

    int k = 0;
    v[0] = 0; z[0] = -1e30f; z[1] = 1e30f;
    for (int q = 1; q < 128; q++) {
        float fqq = FQ(q);
        float s;
        while (true) {
            int vk = v[k];
            s = __fdividef(fqq - FQ(vk), (float)(2 * (q - vk)));
            if (s <= z[k]) k--;
            else break;
        }
        k++;
        v[k] = (unsigned char)q;
        z[k] = s;
        z[k + 1] = 1e30f;
    }
    k = 0;
    for (int x = 0; x < 128; x++) {
        while (z[k + 1] < (float)x) k++;
        int vk = v[k];
        float gx = FQ(vk) + (float)(x * (x - 2 * vk));  // = g[vk] + (x-vk)^2
        dst[base + x * 128 + tid] = gx;                 // coalesced
    }
    #undef FQ
}

// ---------------------------------------------------------------------------
// Pass3 (D axis) fused with HALF the loss each:
//   loss = sum (p-t)^2*(gp+gt) = [sum (p-t)^2*gp] + [sum (p-t)^2*gt]
// so a thread needs only ONE tensor's EDT -> 2x the warps of round 1.
// grid = (512, 2 tensors), block = 128. Thread -> one (bc,h,w) line along D.
// ---------------------------------------------------------------------------
__global__ void __launch_bounds__(128) k_pass3(const float* __restrict__ pred,
                                               const float* __restrict__ target) {
    const float* gsrc = (blockIdx.y == 0) ? g_pred : g_target;
    int t = blockIdx.x * 128 + threadIdx.x;          // 0..65535
    int w  = t & 127;
    int h  = (t >> 7) & 127;
    int bc = t >> 14;
    const long base = (long)bc * BC_STRIDE + (long)h * H_STRIDE + w;

    float fq[128];
    unsigned char v[128];
    float z[129];
    #pragma unroll 4
    for (int i = 0; i < 128; i++)
        fq[i] = gsrc[base + (long)i * D_STRIDE] + (float)(i * i);

    int k = 0;
    v[0] = 0; z[0] = -1e30f; z[1] = 1e30f;
    for (int q = 1; q < 128; q++) {
        float s;
        while (true) {
            int vk = v[k];
            s = __fdividef(fq[q] - fq[vk], (float)(2 * (q - vk)));
            if (s <= z[k]) k--;
            else break;
        }
        k++;
        v[k] = (unsigned char)q;
        z[k] = s;
        z[k + 1] = 1e30f;
    }

    double acc = 0.0;
    k = 0;
    for (int x = 0; x < 128; x++) {
        while (z[k + 1] < (float)x) k++;
        int vk = v[k];
        float gx = fq[vk] + (float)(x * (x - 2 * vk));
        long idx = base + (long)x * D_STRIDE;
        float e = pred[idx] - target[idx];
        acc += (double)(e * e * gx);
    }

    __shared__ double sd[128];
    sd[threadIdx.x] = acc;
    __syncthreads();
    #pragma unroll
    for (int s = 64; s > 0; s >>= 1) {
        if (threadIdx.x < s) sd[threadIdx.x] += sd[threadIdx.x + s];
        __syncthreads();
    }
    if (threadIdx.x == 0) atomicAdd(&g_acc, sd[0]);
}

__global__ void k_final(float* __restrict__ out, const int* __restrict__ is_avg) {
    double m = g_acc / (double)NTOT;
    if (*is_avg == 0) m *= 2.0;     // * pred.shape[0]
    out[0] = (float)m;
}

extern "C" void kernel_launch(void* const* d_in, const int* in_sizes, int n_in,
                              void* d_out, int out_size) {
    const float* pred   = (const float*)d_in[0];
    const float* target = (const float*)d_in[1];
    const int*   is_avg = (const int*)d_in[2];
    float* out = (float*)d_out;

    k_zero<<<1, 1>>>();
    dim3 g(512, 2);
    k_pass12<<<g, 128>>>(pred, target);
    k_pass3<<<g, 128>>>(pred, target);
    k_final<<<1, 1>>>(out, is_avg);
}

// round 7
// speedup vs baseline: 7.1037x; 5.5121x over previous
#include <cuda_runtime.h>

// pred/target: (2,2,128,128,128) fp32 contiguous.
// Volume index: bc*2^21 + d*2^14 + h*2^7 + w
#define NTOT 8388608
#define BC_STRIDE 2097152
#define D_STRIDE  16384

// Squared-EDT after W+H passes is an integer <= 127^2+127^2 = 32258 -> u16.
// 65535 = "infinity" sentinel (whole slab foreground; cannot occur for this data).
__device__ unsigned short g_p16[NTOT];
__device__ unsigned short g_t16[NTOT];
__device__ double g_acc;

__global__ void k_zero() { g_acc = 0.0; }

// ---------------------------------------------------------------------------
// Fused pass1 (W axis, binary two-sweep) + pass2 (H axis, pruned exact scan)
// One (bc,d) slab of 128x128 per block. grid=(512, 2 tensors), block=256.
// Shared tiles u16 with 130-col pad (65-word odd row stride => lanes that
// walk consecutive rows at fixed col hit distinct banks).
// ---------------------------------------------------------------------------
__global__ void __launch_bounds__(256) k_pass12(const float* __restrict__ pred,
                                                const float* __restrict__ target) {
    __shared__ unsigned short dsq[128][130];   // W-distance, then its square
    __shared__ unsigned short outT[128][130];  // pass2 result
    const float* src = blockIdx.y ? target : pred;
    unsigned short* dst = blockIdx.y ? g_t16 : g_p16;
    const int tid = threadIdx.x;
    const long base = (long)blockIdx.x * 16384;

    // mask load (coalesced): 0 = background, 255 = foreground sentinel
    #pragma unroll
    for (int it = 0; it < 64; it++) {
        int idx = it * 256 + tid;
        dsq[idx >> 7][idx & 127] = (src[base + idx] >= 0.5f) ? 255 : 0;
    }
    __syncthreads();

    // pass1: two integer sweeps along w (thread = row h). 255 = "no bg yet".
    if (tid < 128) {
        unsigned short* row = dsq[tid];
        int d = 255;
        #pragma unroll 4
        for (int w = 0; w < 128; w++) {
            d = (row[w] == 0) ? 0 : min(d + 1, 255);
            row[w] = (unsigned short)d;
        }
        int db = 255;
        #pragma unroll 4
        for (int w = 127; w >= 0; w--) {
            int df = row[w];
            db = (df == 0) ? 0 : min(db + 1, 255);
            row[w] = (unsigned short)min(df, db);
        }
    }
    __syncthreads();

    // square in place (sentinel 255 -> 65535)
    #pragma unroll
    for (int it = 0; it < 64; it++) {
        int idx = it * 256 + tid;
        int r = idx >> 7, w = idx & 127;
        int d = dsq[r][w];
        dsq[r][w] = (d == 255) ? (unsigned short)65535 : (unsigned short)(d * d);
    }
    __syncthreads();

    // pass2: out[x][w] = min_y (dsq[y][w] + (x-y)^2), pruned outward scan.
    // Warp per column (all lanes same w -> broadcast-free, conflict-free rows).
    const int warp = tid >> 5, lane = tid & 31;
    for (int c = 0; c < 16; c++) {
        int w = warp * 16 + c;
        #pragma unroll
        for (int m = 0; m < 4; m++) {
            int x = lane + 32 * m;
            int b = dsq[x][w];                 // r = 0 candidate
            int rr = 1;                        // r^2
            for (int r = 1; r < 128; r++) {
                if (__all_sync(0xffffffffu, rr >= b)) break;  // uniform exit
                int lo = x - r, hi = x + r;
                if (lo >= 0)  b = min(b, (int)dsq[lo][w] + rr);
                if (hi < 128) b = min(b, (int)dsq[hi][w] + rr);
                rr += 2 * r + 1;
            }
            // true values <= 32258; anything larger came from the sentinel
            outT[x][w] = (b > 32258) ? (unsigned short)65535 : (unsigned short)b;
        }
    }
    __syncthreads();

    #pragma unroll
    for (int it = 0; it < 64; it++) {
        int idx = it * 256 + tid;
        dst[base + idx] = outT[idx >> 7][idx & 127];   // coalesced u16 store
    }
}

// ---------------------------------------------------------------------------
// Pass3 (D axis, pruned scan for BOTH tensors) fused with the loss reduction.
// Block = 512 threads, tile = fixed (bc,h), w0..w0+63, all 128 d.
// grid = (2 w-groups, 128 h, 4 bc).
// ---------------------------------------------------------------------------
__global__ void __launch_bounds__(512) k_pass3(const float* __restrict__ pred,
                                               const float* __restrict__ target) {
    __shared__ unsigned short gp[128][66];   // 33-word odd row stride
    __shared__ unsigned short gt[128][66];
    __shared__ float esum[128][65];          // edt_p^2 + edt_t^2 (exact ints in f32)
    __shared__ double sd[512];

    const int tid = threadIdx.x;
    const int w0 = blockIdx.x * 64;
    const int h  = blockIdx.y;
    const int bc = blockIdx.z;
    const long base = (long)bc * BC_STRIDE + (long)h * 128 + w0;

    // stage g tiles (coalesced)
    #pragma unroll
    for (int it = 0; it < 16; it++) {
        int idx = it * 512 + tid;            // 8192 elems
        int d = idx >> 6, w = idx & 63;
        long a = base + (long)d * D_STRIDE + w;
        gp[d][w] = g_p16[a];
        gt[d][w] = g_t16[a];
    }
    __syncthreads();

    // pruned scans along d, both tensors in one loop (shared r walk)
    const int warp = tid >> 5, lane = tid & 31;
    for (int c = 0; c < 4; c++) {
        int w = warp * 4 + c;
        #pragma unroll
        for (int m = 0; m < 4; m++) {
            int x = lane + 32 * m;
            int bp = gp[x][w];
            int bt = gt[x][w];
            int rr = 1;
            for (int r = 1; r < 128; r++) {
                int bmax = max(bp, bt);
                if (__all_sync(0xffffffffu, rr >= bmax)) break;
                int lo = x - r, hi = x + r;
                if (lo >= 0) {
                    bp = min(bp, (int)gp[lo][w] + rr);
                    bt = min(bt, (int)gt[lo][w] + rr);
                }
                if (hi < 128) {
                    bp = min(bp, (int)gp[hi][w] + rr);
                    bt = min(bt, (int)gt[hi][w] + rr);
                }
                rr += 2 * r + 1;
            }
            esum[x][w] = (float)(bp + bt);   // <= 96774: exact in f32
        }
    }
    __syncthreads();

    // loss accumulation (coalesced pred/target reads)
    double acc = 0.0;
    #pragma unroll
    for (int it = 0; it < 16; it++) {
        int idx = it * 512 + tid;
        int d = idx >> 6, w = idx & 63;
        long a = base + (long)d * D_STRIDE + w;
        float e = pred[a] - target[a];
        acc += (double)(e * e * esum[d][w]);
    }

    sd[tid] = acc;
    __syncthreads();
    #pragma unroll
    for (int s = 256; s > 0; s >>= 1) {
        if (tid < s) sd[tid] += sd[tid + s];
        __syncthreads();
    }
    if (tid == 0) atomicAdd(&g_acc, sd[0]);
}

__global__ void k_final(float* __restrict__ out, const int* __restrict__ is_avg) {
    double m = g_acc / (double)NTOT;
    if (*is_avg == 0) m *= 2.0;   // * pred.shape[0]
    out[0] = (float)m;
}

extern "C" void kernel_launch(void* const* d_in, const int* in_sizes, int n_in,
                              void* d_out, int out_size) {
    const float* pred   = (const float*)d_in[0];
    const float* target = (const float*)d_in[1];
    const int*   is_avg = (const int*)d_in[2];
    float* out = (float*)d_out;

    k_zero<<<1, 1>>>();
    k_pass12<<<dim3(512, 2), 256>>>(pred, target);
    k_pass3<<<dim3(2, 128, 4), 512>>>(pred, target);
    k_final<<<1, 1>>>(out, is_avg);
}

// round 8
// speedup vs baseline: 10.3299x; 1.4541x over previous
#include <cuda_runtime.h>

// pred/target: (2,2,128,128,128) fp32 contiguous. idx = bc*2^21 + d*2^14 + h*2^7 + w
#define NTOT 8388608
#define BC_STRIDE 2097152
#define D_STRIDE  16384

// Squared EDT after W+H passes: integer <= 32258 -> u16. 65535 = inf sentinel.
__device__ unsigned short g_p16[NTOT];
__device__ unsigned short g_t16[NTOT];
__device__ double g_acc;

// ---------------------------------------------------------------------------
// Fused pass1 (W axis, two-sweep + square) + pass2 (H axis, pruned exact scan)
// One (bc,d) slab 128x128 per block. grid=(512, 2 tensors), block=256.
// dsq stride 130 u16 (65 words, odd) => pass1 column access conflict-free;
// pass2 reads/stores are row-wise (lanes = consecutive w) => conflict-free.
// ---------------------------------------------------------------------------
__global__ void __launch_bounds__(256) k_pass12(const float* __restrict__ pred,
                                                const float* __restrict__ target) {
    __shared__ unsigned short dsq[128][130];
    const float* src = blockIdx.y ? target : pred;
    unsigned short* dst = blockIdx.y ? g_t16 : g_p16;
    const int tid = threadIdx.x;
    const long base = (long)blockIdx.x * 16384;

    if (blockIdx.x == 0 && blockIdx.y == 0 && tid == 0) g_acc = 0.0;  // fold k_zero

    // vectorized mask load: 0 = background, 255 = foreground
    const float4* src4 = (const float4*)(src + base);
    #pragma unroll
    for (int it = 0; it < 16; it++) {
        int idx = it * 256 + tid;            // 0..4095 float4
        float4 v = src4[idx];
        int r  = idx >> 5;                   // 32 float4 per row
        int w4 = (idx & 31) * 4;
        *(ushort2*)&dsq[r][w4]     = make_ushort2(v.x >= 0.5f ? 255 : 0,
                                                  v.y >= 0.5f ? 255 : 0);
        *(ushort2*)&dsq[r][w4 + 2] = make_ushort2(v.z >= 0.5f ? 255 : 0,
                                                  v.w >= 0.5f ? 255 : 0);
    }
    __syncthreads();

    // pass1: forward/backward sweep along w (thread = row h); square folded in.
    if (tid < 128) {
        unsigned short* row = dsq[tid];
        int d = 255;
        #pragma unroll 4
        for (int w = 0; w < 128; w++) {
            d = (row[w] == 0) ? 0 : min(d + 1, 255);
            row[w] = (unsigned short)d;
        }
        int db = 255;
        #pragma unroll 4
        for (int w = 127; w >= 0; w--) {
            int df = row[w];
            db = (df == 0) ? 0 : min(db + 1, 255);
            int m = min(df, db);
            row[w] = (m == 255) ? (unsigned short)65535 : (unsigned short)(m * m);
        }
    }
    __syncthreads();

    // pass2: out[x][w] = min_y (dsq[y][w] + (x-y)^2), pruned outward scan.
    // warp = output row x, lanes = 32 consecutive w -> coalesced global store.
    const int warp = tid >> 5, lane = tid & 31;
    for (int i = 0; i < 16; i++) {
        int x = warp + 8 * i;
        #pragma unroll
        for (int wg = 0; wg < 4; wg++) {
            int w = wg * 32 + lane;
            int b = dsq[x][w];
            int rr = 1;
            for (int r = 1; r < 128; r++) {
                if (__all_sync(0xffffffffu, rr >= b)) break;
                int lo = x - r, hi = x + r;
                if (lo >= 0)  b = min(b, (int)dsq[lo][w] + rr);
                if (hi < 128) b = min(b, (int)dsq[hi][w] + rr);
                rr += 2 * r + 1;
            }
            dst[base + x * 128 + w] =
                (b > 32258) ? (unsigned short)65535 : (unsigned short)b;
        }
    }
}

// ---------------------------------------------------------------------------
// Pass3 (D axis, pruned scan, both tensors) fused with the loss reduction.
// Block = 512, tile = fixed (bc,h), w0..w0+63, all 128 d. grid=(2,128,4).
// warp = fixed d (=x), lanes = 32 consecutive w -> coalesced pred/target loads,
// loss accumulated inline (no esum staging).
// ---------------------------------------------------------------------------
__global__ void __launch_bounds__(512) k_pass3(const float* __restrict__ pred,
                                               const float* __restrict__ target) {
    __shared__ unsigned short gp[128][66];
    __shared__ unsigned short gt[128][66];
    __shared__ double sd[16];

    const int tid = threadIdx.x;
    const int w0 = blockIdx.x * 64;
    const int h  = blockIdx.y;
    const int bc = blockIdx.z;
    const long base = (long)bc * BC_STRIDE + (long)h * 128 + w0;

    // stage g tiles (coalesced ushort2 loads: 64 u16 = 128B per row)
    #pragma unroll
    for (int it = 0; it < 8; it++) {
        int idx = it * 512 + tid;            // 0..4095 ushort2
        int d = idx >> 5, w2 = (idx & 31) * 2;
        long a = base + (long)d * D_STRIDE + w2;
        *(ushort2*)&gp[d][w2] = *(const ushort2*)&g_p16[a];
        *(ushort2*)&gt[d][w2] = *(const ushort2*)&g_t16[a];
    }
    __syncthreads();

    // pruned scans along d + inline loss
    const int warp = tid >> 5, lane = tid & 31;
    double acc = 0.0;
    for (int i = 0; i < 8; i++) {
        int x = warp + 16 * i;
        #pragma unroll
        for (int wg = 0; wg < 2; wg++) {
            int w = wg * 32 + lane;
            int bp = gp[x][w];
            int bt = gt[x][w];
            int rr = 1;
            for (int r = 1; r < 128; r++) {
                if (__all_sync(0xffffffffu, rr >= max(bp, bt))) break;
                int lo = x - r, hi = x + r;
                if (lo >= 0) {
                    bp = min(bp, (int)gp[lo][w] + rr);
                    bt = min(bt, (int)gt[lo][w] + rr);
                }
                if (hi < 128) {
                    bp = min(bp, (int)gp[hi][w] + rr);
                    bt = min(bt, (int)gt[hi][w] + rr);
                }
                rr += 2 * r + 1;
            }
            long a = base + (long)x * D_STRIDE + w;
            float e = pred[a] - target[a];               // coalesced 128B
            acc += (double)(e * e * (float)(bp + bt));   // <= 96774: exact f32
        }
    }

    // warp-shuffle reduce, then cross-warp
    #pragma unroll
    for (int s = 16; s > 0; s >>= 1)
        acc += __shfl_down_sync(0xffffffffu, acc, s);
    if (lane == 0) sd[warp] = acc;
    __syncthreads();
    if (warp == 0) {
        double v = (lane < 16) ? sd[lane] : 0.0;
        #pragma unroll
        for (int s = 8; s > 0; s >>= 1)
            v += __shfl_down_sync(0xffffffffu, v, s);
        if (lane == 0) atomicAdd(&g_acc, v);
    }
}

__global__ void k_final(float* __restrict__ out, const int* __restrict__ is_avg) {
    double m = g_acc / (double)NTOT;
    if (*is_avg == 0) m *= 2.0;   // * pred.shape[0]
    out[0] = (float)m;
}

extern "C" void kernel_launch(void* const* d_in, const int* in_sizes, int n_in,
                              void* d_out, int out_size) {
    const float* pred   = (const float*)d_in[0];
    const float* target = (const float*)d_in[1];
    const int*   is_avg = (const int*)d_in[2];
    float* out = (float*)d_out;

    k_pass12<<<dim3(512, 2), 256>>>(pred, target);
    k_pass3<<<dim3(2, 128, 4), 512>>>(pred, target);
    k_final<<<1, 1>>>(out, is_avg);
}